// round 7
// baseline (speedup 1.0000x reference)
#include <cuda_runtime.h>

// Atomic partial-output accumulators, one 128B L2 line per output so the 6
// counters serialize independently. Zero at module load; last warp of each
// launch resets them, so every graph replay starts identically.
__device__ float g_acc[6 * 32];
// Warp-completion ticket (256 warps total), self-resetting.
__device__ int g_ticket = 0;

#define NBLK 32                     // 32 blocks x 8 warps = 256 rows, warp-per-row
#define NWARPS_TOTAL 256

__device__ __forceinline__ float dot4(float4 a, float4 b) {
    return a.x * b.x + a.y * b.y + a.z * b.z + a.w * b.w;
}

__global__ void __launch_bounds__(256, 1)
actor_fused_kernel(const float* __restrict__ x,
                   const float* __restrict__ conv_w, const float* __restrict__ conv_b,
                   const float* __restrict__ w0, const float* __restrict__ b0,
                   const float* __restrict__ w1, const float* __restrict__ b1,
                   const float* __restrict__ w2, const float* __restrict__ b2,
                   const float* __restrict__ w3, const float* __restrict__ b3,
                   const float* __restrict__ w4, const float* __restrict__ b4,
                   float* __restrict__ out) {
    __shared__ __align__(16) float h[2048];

    const int tid  = threadIdx.x;
    const int lane = tid & 31;
    const int wid  = tid >> 5;
    const int row  = blockIdx.x * 8 + wid;     // this warp's w3/h2 row

    // ================= Front-batched independent loads =================
    // All issued back-to-back; steady-state these are L2 hits (~250 cyc),
    // MLP=16+ covers the latency.

    // w3 row slice: 16 float4 per lane, coalesced (lane + 32*j)
    const float4* wr = reinterpret_cast<const float4*>(w3 + (size_t)row * 2048);
    float4 wv[16];
    #pragma unroll
    for (int j = 0; j < 16; j++) wv[j] = wr[lane + 32 * j];

    // conv weights for this thread's channel
    const int c = tid & 127;
    const float4 cw = *reinterpret_cast<const float4*>(conv_w + c * 4);
    const float  cb = conv_b[c];

    // x values (scalar broadcasts + per-half float4 windows)
    const float x7 = x[7], x15 = x[15], x39 = x[39];
    const int lohw = (tid < 128);
    const float4 xA0 = *reinterpret_cast<const float4*>(x + (lohw ? 16 : 24));
    const float4 xA1 = *reinterpret_cast<const float4*>(x + (lohw ? 20 : 28));
    const float4 xB0 = *reinterpret_cast<const float4*>(x + 32);
    const float4 xB1 = *reinterpret_cast<const float4*>(x + 36);

    // scalar-affine branch params
    const float w0v = w0[c], b0v = b0[c];
    const float w1v = w1[c], b1v = b1[c];
    const float w2v = w2[c], b2v = b2[c];

    // per-row bias (uniform across warp)
    const float b3r = b3[row];

    // w4 column entry for this warp's row: lanes 0..5 handle outputs 0..5
    const float w4v = w4[(lane < 6 ? lane : 0) * 256 + row];
    const float b4p = b4[lane < 6 ? lane : 0];

    // ================= Build h[2048] in smem =================
    // h[   0: 128) = relu(w0*x[0,7] + b0)
    // h[ 128: 256) = relu(w1*x[1,7] + b1)
    // h[ 256: 896) = relu(conv1d(x[2,0:8]))  channel-major [128,5]
    // h[ 896:1536) = relu(conv1d(x[3,0:8]))  channel-major [128,5]
    // h[1536:1920) = relu(conv1d(x[4,0:6]))  channel-major [128,3]
    // h[1920:2048) = w2*x[4,7] + b2          (NO relu)
    {
        float xw[8];
        xw[0] = xA0.x; xw[1] = xA0.y; xw[2] = xA0.z; xw[3] = xA0.w;
        xw[4] = xA1.x; xw[5] = xA1.y; xw[6] = xA1.z; xw[7] = xA1.w;

        if (lohw) {
            h[c]        = fmaxf(fmaf(w0v, x7,  b0v), 0.0f);
            h[128 + c]  = fmaxf(fmaf(w1v, x15, b1v), 0.0f);
            h[1920 + c] =       fmaf(w2v, x39, b2v);   // no relu
            #pragma unroll
            for (int t = 0; t < 5; t++) {
                float s = fmaf(cw.x, xw[t],
                          fmaf(cw.y, xw[t + 1],
                          fmaf(cw.z, xw[t + 2],
                          fmaf(cw.w, xw[t + 3], cb))));
                h[256 + c * 5 + t] = fmaxf(s, 0.0f);
            }
        } else {
            #pragma unroll
            for (int t = 0; t < 5; t++) {
                float s = fmaf(cw.x, xw[t],
                          fmaf(cw.y, xw[t + 1],
                          fmaf(cw.z, xw[t + 2],
                          fmaf(cw.w, xw[t + 3], cb))));
                h[896 + c * 5 + t] = fmaxf(s, 0.0f);
            }
            float xv[8];
            xv[0] = xB0.x; xv[1] = xB0.y; xv[2] = xB0.z; xv[3] = xB0.w;
            xv[4] = xB1.x; xv[5] = xB1.y; xv[6] = xB1.z; xv[7] = xB1.w;
            #pragma unroll
            for (int t = 0; t < 3; t++) {
                float s = fmaf(cw.x, xv[t],
                          fmaf(cw.y, xv[t + 1],
                          fmaf(cw.z, xv[t + 2],
                          fmaf(cw.w, xv[t + 3], cb))));
                h[1536 + c * 3 + t] = fmaxf(s, 0.0f);
            }
        }
    }
    __syncthreads();                 // BAR1: h ready (the ONLY block barrier)

    // ======== This warp's row dot: p = w3[row,:] @ h ========
    const float4* hv = reinterpret_cast<const float4*>(h);
    float p = 0.0f;
    #pragma unroll
    for (int j = 0; j < 16; j++)
        p += dot4(wv[j], hv[lane + 32 * j]);

    // Butterfly reduce: all lanes end with the full row sum (no broadcast step)
    #pragma unroll
    for (int o = 16; o > 0; o >>= 1)
        p += __shfl_xor_sync(0xFFFFFFFFu, p, o);

    const float h2 = fmaxf(p + b3r, 0.0f);

    // lanes 0..5: partial outputs g_acc[w] += w4[w][row] * h2
    if (lane < 6)
        atomicAdd(&g_acc[lane * 32], h2 * w4v);
    __syncwarp();                    // all 6 REDs issued before the ticket

    // ======== Per-warp ticket; warp 255 runs the fused tail ========
    int t = 0;
    if (lane == 0) {
        __threadfence();             // release this warp's REDs to device scope
        t = atomicAdd(&g_ticket, 1);
    }
    t = __shfl_sync(0xFFFFFFFFu, t, 0);
    if (t == NWARPS_TOTAL - 1) {
        __threadfence();             // acquire: all warps' REDs visible
        if (lane < 6) {
            float acc = __ldcg(&g_acc[lane * 32]);
            out[lane] = acc + b4p;
            g_acc[lane * 32] = 0.0f; // reset for next replay
        }
        if (lane == 0) g_ticket = 0;
    }
}

extern "C" void kernel_launch(void* const* d_in, const int* in_sizes, int n_in,
                              void* d_out, int out_size) {
    const float* x      = (const float*)d_in[0];
    const float* conv_w = (const float*)d_in[1];
    const float* conv_b = (const float*)d_in[2];
    const float* w0 = (const float*)d_in[3];
    const float* b0 = (const float*)d_in[4];
    const float* w1 = (const float*)d_in[5];
    const float* b1 = (const float*)d_in[6];
    const float* w2 = (const float*)d_in[7];
    const float* b2 = (const float*)d_in[8];
    const float* w3 = (const float*)d_in[9];
    const float* b3 = (const float*)d_in[10];
    const float* w4 = (const float*)d_in[11];
    const float* b4 = (const float*)d_in[12];
    float* out = (float*)d_out;

    actor_fused_kernel<<<NBLK, 256>>>(x, conv_w, conv_b,
                                      w0, b0, w1, b1, w2, b2, w3, b3,
                                      w4, b4, out);
}

// round 9
// speedup vs baseline: 1.0332x; 1.0332x over previous
#include <cuda_runtime.h>

// Atomic partial-output accumulators, one 128B L2 line per output so the 6
// counters serialize independently at the LTS. Zero at module load; the last
// block of each launch resets them, so every graph replay starts identically.
__device__ float g_acc[6 * 32];
// Last-block-done ticket, self-resetting.
__device__ int g_ticket = 0;

#define RPB 2                       // w3 rows per block
#define NBLK (256 / RPB)            // 128 blocks = one wave

__device__ __forceinline__ float dot4(float4 a, float4 b) {
    return a.x * b.x + a.y * b.y + a.z * b.z + a.w * b.w;
}

// Compute 8 consecutive conv-branch h values entirely in registers.
// q0 = first flat conv index (channel-major: q = c*D + t), D in {5,3}.
// All loads are front-batched (indices computable at entry).
template <int D>
__device__ __forceinline__ void conv8(const float* __restrict__ conv_w,
                                      const float* __restrict__ conv_b,
                                      const float* __restrict__ x, int xbase,
                                      int q0, float* h8) {
    float4 cw[8]; float cb[8]; float xv[8][4];
    #pragma unroll
    for (int k = 0; k < 8; k++) {
        const int q = q0 + k;
        const int c = q / D;
        const int t = q - c * D;
        cw[k] = *reinterpret_cast<const float4*>(conv_w + 4 * c);
        cb[k] = conv_b[c];
        #pragma unroll
        for (int m = 0; m < 4; m++) xv[k][m] = x[xbase + t + m];
    }
    #pragma unroll
    for (int k = 0; k < 8; k++) {
        float s = fmaf(cw[k].x, xv[k][0],
                  fmaf(cw[k].y, xv[k][1],
                  fmaf(cw[k].z, xv[k][2],
                  fmaf(cw[k].w, xv[k][3], cb[k]))));
        h8[k] = fmaxf(s, 0.0f);
    }
}

__global__ void __launch_bounds__(256, 1)
actor_fused_kernel(const float* __restrict__ x,
                   const float* __restrict__ conv_w, const float* __restrict__ conv_b,
                   const float* __restrict__ w0, const float* __restrict__ b0,
                   const float* __restrict__ w1, const float* __restrict__ b1,
                   const float* __restrict__ w2, const float* __restrict__ b2,
                   const float* __restrict__ w3, const float* __restrict__ b3,
                   const float* __restrict__ w4, const float* __restrict__ b4,
                   float* __restrict__ out) {
    __shared__ float red[RPB][8];

    const int tid  = threadIdx.x;
    const int lane = tid & 31;
    const int row0 = blockIdx.x * RPB;
    const int i0   = tid * 8;          // this thread's h slice [i0, i0+8)

    // ---- w3 slices for this block's 2 rows (4x LDG.128, coalesced) ----
    const float4* wr0 = reinterpret_cast<const float4*>(w3 + (size_t)row0 * 2048);
    const float4* wr1 = reinterpret_cast<const float4*>(w3 + (size_t)(row0 + 1) * 2048);
    const float4 a0 = wr0[tid * 2], a1 = wr0[tid * 2 + 1];
    const float4 c0 = wr1[tid * 2], c1 = wr1[tid * 2 + 1];

    // ---- tail params ----
    const float b3p = b3[row0 + (tid & 1)];
    const int  widx = (tid < 12) ? ((tid >> 1) * 256 + row0 + (tid & 1)) : row0;
    const float w4v = w4[widx];
    const float b4p = b4[lane < 6 ? lane : 0];

    // ---- This thread's 8 h values, entirely in registers. Segment
    //      boundaries (128,256,896,1536,1920) are multiples of 8, so each
    //      thread's slice lies in exactly one branch. Layout:
    // h[   0: 128) = relu(w0*x[0,7] + b0)
    // h[ 128: 256) = relu(w1*x[1,7] + b1)
    // h[ 256: 896) = relu(conv1d(x[2,0:8]))  channel-major [128,5]
    // h[ 896:1536) = relu(conv1d(x[3,0:8]))  channel-major [128,5]
    // h[1536:1920) = relu(conv1d(x[4,0:6]))  channel-major [128,3]
    // h[1920:2048) = w2*x[4,7] + b2          (NO relu)
    float h8[8];
    if (tid < 16) {
        const float xs = x[7];
        const float4 wA = *reinterpret_cast<const float4*>(w0 + i0);
        const float4 wB = *reinterpret_cast<const float4*>(w0 + i0 + 4);
        const float4 bA = *reinterpret_cast<const float4*>(b0 + i0);
        const float4 bB = *reinterpret_cast<const float4*>(b0 + i0 + 4);
        h8[0] = fmaxf(fmaf(wA.x, xs, bA.x), 0.0f);
        h8[1] = fmaxf(fmaf(wA.y, xs, bA.y), 0.0f);
        h8[2] = fmaxf(fmaf(wA.z, xs, bA.z), 0.0f);
        h8[3] = fmaxf(fmaf(wA.w, xs, bA.w), 0.0f);
        h8[4] = fmaxf(fmaf(wB.x, xs, bB.x), 0.0f);
        h8[5] = fmaxf(fmaf(wB.y, xs, bB.y), 0.0f);
        h8[6] = fmaxf(fmaf(wB.z, xs, bB.z), 0.0f);
        h8[7] = fmaxf(fmaf(wB.w, xs, bB.w), 0.0f);
    } else if (tid < 32) {
        const float xs = x[15];
        const int off = i0 - 128;
        const float4 wA = *reinterpret_cast<const float4*>(w1 + off);
        const float4 wB = *reinterpret_cast<const float4*>(w1 + off + 4);
        const float4 bA = *reinterpret_cast<const float4*>(b1 + off);
        const float4 bB = *reinterpret_cast<const float4*>(b1 + off + 4);
        h8[0] = fmaxf(fmaf(wA.x, xs, bA.x), 0.0f);
        h8[1] = fmaxf(fmaf(wA.y, xs, bA.y), 0.0f);
        h8[2] = fmaxf(fmaf(wA.z, xs, bA.z), 0.0f);
        h8[3] = fmaxf(fmaf(wA.w, xs, bA.w), 0.0f);
        h8[4] = fmaxf(fmaf(wB.x, xs, bB.x), 0.0f);
        h8[5] = fmaxf(fmaf(wB.y, xs, bB.y), 0.0f);
        h8[6] = fmaxf(fmaf(wB.z, xs, bB.z), 0.0f);
        h8[7] = fmaxf(fmaf(wB.w, xs, bB.w), 0.0f);
    } else if (tid < 112) {
        conv8<5>(conv_w, conv_b, x, 16, i0 - 256, h8);
    } else if (tid < 192) {
        conv8<5>(conv_w, conv_b, x, 24, i0 - 896, h8);
    } else if (tid < 240) {
        conv8<3>(conv_w, conv_b, x, 32, i0 - 1536, h8);
    } else {
        const float xs = x[39];
        const int off = i0 - 1920;
        const float4 wA = *reinterpret_cast<const float4*>(w2 + off);
        const float4 wB = *reinterpret_cast<const float4*>(w2 + off + 4);
        const float4 bA = *reinterpret_cast<const float4*>(b2 + off);
        const float4 bB = *reinterpret_cast<const float4*>(b2 + off + 4);
        h8[0] = fmaf(wA.x, xs, bA.x);      // no relu
        h8[1] = fmaf(wA.y, xs, bA.y);
        h8[2] = fmaf(wA.z, xs, bA.z);
        h8[3] = fmaf(wA.w, xs, bA.w);
        h8[4] = fmaf(wB.x, xs, bB.x);
        h8[5] = fmaf(wB.y, xs, bB.y);
        h8[6] = fmaf(wB.z, xs, bB.z);
        h8[7] = fmaf(wB.w, xs, bB.w);
    }

    // ---- partial dots for this block's 2 rows (h never touches memory) ----
    const float4 H0 = make_float4(h8[0], h8[1], h8[2], h8[3]);
    const float4 H1 = make_float4(h8[4], h8[5], h8[6], h8[7]);
    float p0 = dot4(a0, H0) + dot4(a1, H1);
    float p1 = dot4(c0, H0) + dot4(c1, H1);

    // Two independent shuffle chains; scheduler overlaps them.
    #pragma unroll
    for (int o = 16; o > 0; o >>= 1) {
        p0 += __shfl_down_sync(0xFFFFFFFFu, p0, o);
        p1 += __shfl_down_sync(0xFFFFFFFFu, p1, o);
    }
    if (lane == 0) {
        red[0][tid >> 5] = p0;
        red[1][tid >> 5] = p1;
    }
    __syncthreads();                 // the ONLY block barrier

    // ---- Warp 0 only: partial outputs + ticket + fused tail ----
    if (tid < 32) {
        if (tid < 12) {
            const int r = tid & 1;
            // pairwise tree over 8 warp partials (shorter dep chain)
            float s01 = red[r][0] + red[r][1];
            float s23 = red[r][2] + red[r][3];
            float s45 = red[r][4] + red[r][5];
            float s67 = red[r][6] + red[r][7];
            float s = (s01 + s23) + (s45 + s67);
            s = fmaxf(s + b3p, 0.0f);          // b3p = b3[row0 + (tid&1)]
            atomicAdd(&g_acc[(tid >> 1) * 32], s * w4v);
        }
        __syncwarp();                          // REDs happen-before tid0's fence
        int t = 0;
        if (lane == 0) {
            __threadfence();                   // release warp-0 REDs device-wide
            t = atomicAdd(&g_ticket, 1);
        }
        t = __shfl_sync(0xFFFFFFFFu, t, 0);
        if (t == NBLK - 1) {
            __threadfence();                   // acquire: all blocks' REDs visible
            if (lane < 6) {
                float acc = __ldcg(&g_acc[lane * 32]);
                out[lane] = acc + b4p;
                g_acc[lane * 32] = 0.0f;       // reset for next replay
            }
            if (lane == 0) g_ticket = 0;
        }
    }
}

extern "C" void kernel_launch(void* const* d_in, const int* in_sizes, int n_in,
                              void* d_out, int out_size) {
    const float* x      = (const float*)d_in[0];
    const float* conv_w = (const float*)d_in[1];
    const float* conv_b = (const float*)d_in[2];
    const float* w0 = (const float*)d_in[3];
    const float* b0 = (const float*)d_in[4];
    const float* w1 = (const float*)d_in[5];
    const float* b1 = (const float*)d_in[6];
    const float* w2 = (const float*)d_in[7];
    const float* b2 = (const float*)d_in[8];
    const float* w3 = (const float*)d_in[9];
    const float* b3 = (const float*)d_in[10];
    const float* w4 = (const float*)d_in[11];
    const float* b4 = (const float*)d_in[12];
    float* out = (float*)d_out;

    actor_fused_kernel<<<NBLK, 256>>>(x, conv_w, conv_b,
                                      w0, b0, w1, b1, w2, b2, w3, b3,
                                      w4, b4, out);
}